// round 2
// baseline (speedup 1.0000x reference)
#include <cuda_runtime.h>
#include <cstdint>
#include <cstddef>

#define NN 2048
#define MM 64
#define CAT 576           // 256 (h1) + 64 (att) + 256 (if)
#define EPS 1e-5f

// ---------------- scratch (device globals; allocation-free rule) ----------------
__device__ float g_Wcat[768 * 576];          // packed [w1 | watt | wif]
__device__ float g_bcat[576];                // packed [b1 | batt | bif]
__device__ float g_P[2 * NN * 576];          // Pi (part 0), Pj (part 1)
__device__ float g_af[(size_t)NN * 64 * 64]; // attention features [N,M,SD]
__device__ float g_logits[(size_t)NN * 64 * 4];

__device__ __forceinline__ float warp_sum(float v) {
#pragma unroll
    for (int o = 16; o; o >>= 1) v += __shfl_xor_sync(0xffffffffu, v, o);
    return v;
}
__device__ __forceinline__ float warp_max(float v) {
#pragma unroll
    for (int o = 16; o; o >>= 1) v = fmaxf(v, __shfl_xor_sync(0xffffffffu, v, o));
    return v;
}

// 4x4 micro-tile FMA over a 32-deep k-panel.
// ap: [k][row] panel (stride 65), points at row base ty*4
// bp: [k][col] panel (stride 65), points at col base tx*4
__device__ __forceinline__ void micro_fma32(const float* __restrict__ ap,
                                            const float* __restrict__ bp,
                                            float acc[4][4]) {
#pragma unroll 8
    for (int k = 0; k < 32; k++) {
        const float* apk = ap + k * 65;
        const float* bpk = bp + k * 65;
        float a0 = apk[0], a1 = apk[1], a2 = apk[2], a3 = apk[3];
        float b0 = bpk[0], b1 = bpk[1], b2 = bpk[2], b3 = bpk[3];
        acc[0][0] += a0 * b0; acc[0][1] += a0 * b1; acc[0][2] += a0 * b2; acc[0][3] += a0 * b3;
        acc[1][0] += a1 * b0; acc[1][1] += a1 * b1; acc[1][2] += a1 * b2; acc[1][3] += a1 * b3;
        acc[2][0] += a2 * b0; acc[2][1] += a2 * b1; acc[2][2] += a2 * b2; acc[2][3] += a2 * b3;
        acc[3][0] += a3 * b0; acc[3][1] += a3 * b1; acc[3][2] += a3 * b2; acc[3][3] += a3 * b3;
    }
}

// ---------------- K0: pack weights ----------------
__global__ void pack_kernel(const float* __restrict__ w1, const float* __restrict__ watt,
                            const float* __restrict__ wif, const float* __restrict__ b1,
                            const float* __restrict__ batt, const float* __restrict__ bif) {
    int idx = blockIdx.x * blockDim.x + threadIdx.x;
    if (idx < 768 * 576) {
        int r = idx / 576, c = idx - r * 576;
        float v = (c < 256) ? w1[r * 256 + c]
                 : (c < 320) ? watt[r * 64 + (c - 256)]
                             : wif[r * 256 + (c - 320)];
        g_Wcat[idx] = v;
    }
    if (idx < 576) {
        g_bcat[idx] = (idx < 256) ? b1[idx] : (idx < 320) ? batt[idx - 256] : bif[idx - 320];
    }
}

// ---------------- K1: P = x @ Wcat(part)  [64 rows per block] ----------------
__global__ void __launch_bounds__(256) p_kernel(const float* __restrict__ x) {
    extern __shared__ float sm[];
    float* xs = sm;               // [256][65] transposed x tile
    float* wsh = xs + 256 * 65;   // [32][65]

    int nb = blockIdx.x, part = blockIdx.y;
    int t = threadIdx.x, ty = t >> 4, tx = t & 15;

    {
        int row = t >> 2, k0 = (t & 3) * 64;
        const float* src = x + (size_t)(nb * 64 + row) * 256 + k0;
#pragma unroll
        for (int k = 0; k < 64; k += 4) {
            float4 v = *(const float4*)(src + k);
            xs[(k0 + k) * 65 + row] = v.x; xs[(k0 + k + 1) * 65 + row] = v.y;
            xs[(k0 + k + 2) * 65 + row] = v.z; xs[(k0 + k + 3) * 65 + row] = v.w;
        }
    }
    __syncthreads();

    for (int cc = 0; cc < 9; cc++) {
        float acc[4][4] = {};
        for (int kp = 0; kp < 8; kp++) {
            {
                int k = t >> 3, cb = (t & 7) * 8;
                const float* src = g_Wcat + (size_t)(part * 256 + kp * 32 + k) * 576 + cc * 64 + cb;
                float4 v0 = *(const float4*)src, v1 = *(const float4*)(src + 4);
                float* d = wsh + k * 65 + cb;
                d[0] = v0.x; d[1] = v0.y; d[2] = v0.z; d[3] = v0.w;
                d[4] = v1.x; d[5] = v1.y; d[6] = v1.z; d[7] = v1.w;
            }
            __syncthreads();
            micro_fma32(xs + kp * 32 * 65 + ty * 4, wsh + tx * 4, acc);
            __syncthreads();
        }
#pragma unroll
        for (int ri = 0; ri < 4; ri++) {
            float4 v = make_float4(acc[ri][0], acc[ri][1], acc[ri][2], acc[ri][3]);
            *(float4*)(g_P + (size_t)part * NN * 576 +
                       (size_t)(nb * 64 + ty * 4 + ri) * 576 + cc * 64 + tx * 4) = v;
        }
    }
}

// ---------------- K2: fused heavy kernel, one block per n ----------------
__global__ void __launch_bounds__(256) big_kernel(
    const float* __restrict__ IF, const int* __restrict__ ai, const int* __restrict__ aj,
    const float* __restrict__ g1, const float* __restrict__ be1,
    const float* __restrict__ gatt, const float* __restrict__ beatt,
    const float* __restrict__ gif, const float* __restrict__ beif,
    const float* __restrict__ w2, const float* __restrict__ b2,
    const float* __restrict__ g2, const float* __restrict__ be2,
    const float* __restrict__ wpre, const float* __restrict__ bpre,
    const int* __restrict__ mask,
    float* __restrict__ out_newif) {
    extern __shared__ float sm[];
    float* tbuf = sm;                 // [64][577]
    float* ash = tbuf + 64 * 577;     // [256][65]: IF^T, later h1^T
    float* wsh = ash + 256 * 65;      // [32][65]
    int* idxs = (int*)(wsh + 32 * 65);

    const int n = blockIdx.x;
    const int t = threadIdx.x;
    const int ty = t >> 4, tx = t & 15;
    const int lane = t & 31, wid = t >> 5;
    const float NEG = __int_as_float(0xff800000);

    if (t < 64) { idxs[t] = ai[n * 64 + t]; idxs[64 + t] = aj[n * 64 + t]; }

    // load IF tile transposed into ash[k][row]
    {
        int row = t >> 2, k0 = (t & 3) * 64;
        const float* src = IF + ((size_t)(n * 64 + row)) * 256 + k0;
#pragma unroll
        for (int k = 0; k < 64; k += 4) {
            float4 v = *(const float4*)(src + k);
            ash[(k0 + k) * 65 + row] = v.x; ash[(k0 + k + 1) * 65 + row] = v.y;
            ash[(k0 + k + 2) * 65 + row] = v.z; ash[(k0 + k + 3) * 65 + row] = v.w;
        }
    }
    __syncthreads();

    // -------- Phase 1: t = IF @ Wf + Pi[i] + Pj[j] + bcat --------
    for (int cc = 0; cc < 9; cc++) {
        float acc[4][4] = {};
        for (int kp = 0; kp < 8; kp++) {
            {
                int k = t >> 3, cb = (t & 7) * 8;
                const float* src = g_Wcat + (size_t)(512 + kp * 32 + k) * 576 + cc * 64 + cb;
                float4 v0 = *(const float4*)src, v1 = *(const float4*)(src + 4);
                float* d = wsh + k * 65 + cb;
                d[0] = v0.x; d[1] = v0.y; d[2] = v0.z; d[3] = v0.w;
                d[4] = v1.x; d[5] = v1.y; d[6] = v1.z; d[7] = v1.w;
            }
            __syncthreads();
            micro_fma32(ash + kp * 32 * 65 + ty * 4, wsh + tx * 4, acc);
            __syncthreads();
        }
        int c0 = cc * 64 + tx * 4;
        const float4 bb = *(const float4*)(g_bcat + c0);
#pragma unroll
        for (int ri = 0; ri < 4; ri++) {
            int r = ty * 4 + ri;
            float4 pi = *(const float4*)(g_P + (size_t)idxs[r] * 576 + c0);
            float4 pj = *(const float4*)(g_P + (size_t)NN * 576 + (size_t)idxs[64 + r] * 576 + c0);
            float* dst = tbuf + r * 577 + c0;
            dst[0] = acc[ri][0] + pi.x + pj.x + bb.x;
            dst[1] = acc[ri][1] + pi.y + pj.y + bb.y;
            dst[2] = acc[ri][2] + pi.z + pj.z + bb.z;
            dst[3] = acc[ri][3] + pi.w + pj.w + bb.w;
        }
    }
    __syncthreads();

    // -------- Phase 2: relu + LayerNorm per segment; h1 -> ash transposed --------
    const float inv256 = 1.0f / 256.0f, inv64 = 1.0f / 64.0f;
    for (int rr = 0; rr < 8; rr++) {
        int row = rr * 8 + wid;
        const float* trow = tbuf + row * 577;
        // seg1: cols [0,256) -> h1 (normalized, transposed into ash)
        {
            float v[8], s = 0.f, q = 0.f;
#pragma unroll
            for (int j = 0; j < 8; j++) {
                float xv = fmaxf(trow[lane + j * 32], 0.f);
                v[j] = xv; s += xv; q += xv * xv;
            }
            s = warp_sum(s); q = warp_sum(q);
            float mu = s * inv256, var = q * inv256 - mu * mu;
            float rstd = rsqrtf(var + EPS);
#pragma unroll
            for (int j = 0; j < 8; j++) {
                int c = lane + j * 32;
                ash[c * 65 + row] = (v[j] - mu) * rstd * g1[c] + be1[c];
            }
        }
        // seg2: cols [256,320) -> attention features
        {
            float x0 = fmaxf(trow[256 + lane], 0.f), x1 = fmaxf(trow[288 + lane], 0.f);
            float s = warp_sum(x0 + x1), q = warp_sum(x0 * x0 + x1 * x1);
            float mu = s * inv64, var = q * inv64 - mu * mu;
            float rstd = rsqrtf(var + EPS);
            float* dst = g_af + ((size_t)n * 64 + row) * 64;
            dst[lane] = (x0 - mu) * rstd * gatt[lane] + beatt[lane];
            dst[32 + lane] = (x1 - mu) * rstd * gatt[32 + lane] + beatt[32 + lane];
        }
        // seg3: cols [320,576) -> new interaction features (direct to output)
        {
            float v[8], s = 0.f, q = 0.f;
#pragma unroll
            for (int j = 0; j < 8; j++) {
                float xv = fmaxf(trow[320 + lane + j * 32], 0.f);
                v[j] = xv; s += xv; q += xv * xv;
            }
            s = warp_sum(s); q = warp_sum(q);
            float mu = s * inv256, var = q * inv256 - mu * mu;
            float rstd = rsqrtf(var + EPS);
            float* dst = out_newif + ((size_t)n * 64 + row) * 256;
#pragma unroll
            for (int j = 0; j < 8; j++) {
                int c = lane + j * 32;
                dst[c] = (v[j] - mu) * rstd * gif[c] + beif[c];
            }
        }
    }
    __syncthreads();

    // -------- Phase 3: t2 = h1 @ w2 + b2 (into tbuf cols [320,576)) --------
    for (int cc = 0; cc < 4; cc++) {
        float acc[4][4] = {};
        for (int kp = 0; kp < 8; kp++) {
            {
                int k = t >> 3, cb = (t & 7) * 8;
                const float* src = w2 + (size_t)(kp * 32 + k) * 256 + cc * 64 + cb;
                float4 v0 = *(const float4*)src, v1 = *(const float4*)(src + 4);
                float* d = wsh + k * 65 + cb;
                d[0] = v0.x; d[1] = v0.y; d[2] = v0.z; d[3] = v0.w;
                d[4] = v1.x; d[5] = v1.y; d[6] = v1.z; d[7] = v1.w;
            }
            __syncthreads();
            micro_fma32(ash + kp * 32 * 65 + ty * 4, wsh + tx * 4, acc);
            __syncthreads();
        }
        int c0 = cc * 64 + tx * 4;
        const float4 bb = *(const float4*)(b2 + c0);
#pragma unroll
        for (int ri = 0; ri < 4; ri++) {
            int r = ty * 4 + ri;
            float* dst = tbuf + r * 577 + 320 + c0;
            dst[0] = acc[ri][0] + bb.x; dst[1] = acc[ri][1] + bb.y;
            dst[2] = acc[ri][2] + bb.z; dst[3] = acc[ri][3] + bb.w;
        }
    }
    __syncthreads();

    // -------- Phase 4: h2 = LN(relu(t2)); logits = h2 @ wpre + bpre; mask --------
    for (int rr = 0; rr < 8; rr++) {
        int row = rr * 8 + wid;
        const float* trow = tbuf + row * 577 + 320;
        float v[8], s = 0.f, q = 0.f;
#pragma unroll
        for (int j = 0; j < 8; j++) {
            float xv = fmaxf(trow[lane + j * 32], 0.f);
            v[j] = xv; s += xv; q += xv * xv;
        }
        s = warp_sum(s); q = warp_sum(q);
        float mu = s * inv256, var = q * inv256 - mu * mu;
        float rstd = rsqrtf(var + EPS);
        float l0 = 0.f, l1 = 0.f, l2 = 0.f, l3 = 0.f;
#pragma unroll
        for (int j = 0; j < 8; j++) {
            int c = lane + j * 32;
            float y = (v[j] - mu) * rstd * g2[c] + be2[c];
            float4 wp = *(const float4*)(wpre + (size_t)c * 4);
            l0 += y * wp.x; l1 += y * wp.y; l2 += y * wp.z; l3 += y * wp.w;
        }
        l0 = warp_sum(l0); l1 = warp_sum(l1); l2 = warp_sum(l2); l3 = warp_sum(l3);
        if (lane == 0) {
            bool mk = mask[n * 64 + row] != 0;
            float4 o4;
            o4.x = mk ? NEG : (l0 + bpre[0]);
            o4.y = mk ? NEG : (l1 + bpre[1]);
            o4.z = mk ? NEG : (l2 + bpre[2]);
            o4.w = mk ? NEG : (l3 + bpre[3]);
            *(float4*)(g_logits + ((size_t)n * 64 + row) * 4) = o4;
        }
    }
}

// ---------------- K3: top-k softmax + aggregate + final MLP ----------------
__global__ void __launch_bounds__(256) final_kernel(
    const float* __restrict__ wg, const float* __restrict__ bg,
    const float* __restrict__ gg, const float* __restrict__ beg,
    float* __restrict__ out) {
    __shared__ float afs[64 * 65];
    __shared__ float ws[4 * 64];
    __shared__ float aggs[256];
    __shared__ float red[16];
    int n = blockIdx.x, t = threadIdx.x, lane = t & 31, wid = t >> 5;
    const float NEG = __int_as_float(0xff800000);

    for (int i = t; i < 4096; i += 256) {
        int m = i >> 6, d = i & 63;
        afs[m * 65 + d] = g_af[((size_t)n * 64 + m) * 64 + d];
    }

    if (wid < 4) {
        int h = wid;
        const float* lp = g_logits + (size_t)n * 64 * 4;
        float v0 = lp[lane * 4 + h], v1 = lp[(32 + lane) * 4 + h];
        float c0 = v0, c1 = v1;
        float thr = NEG, maxv = NEG;
#pragma unroll 1
        for (int it = 0; it < 16; it++) {
            float loc = fmaxf(c0, c1);
            float m = warp_max(loc);
            if (it == 0) maxv = m;
            if (m == NEG) break;   // only -inf left: all finite already kept
            thr = m;
            unsigned bl = __ballot_sync(0xffffffffu, loc == m);
            int src = __ffs(bl) - 1;
            if (lane == src) { if (c0 == m) c0 = NEG; else c1 = NEG; }
        }
        float e0 = (v0 >= thr) ? expf(v0 - maxv) : 0.f;
        float e1 = (v1 >= thr) ? expf(v1 - maxv) : 0.f;
        float ssum = warp_sum(e0 + e1);
        float inv = 1.f / ssum;
        ws[h * 64 + lane] = e0 * inv;
        ws[h * 64 + 32 + lane] = e1 * inv;
    }
    __syncthreads();

    {   // agg[d,h] = sum_m w[h,m] * af[m,d];  flat index t = d*4 + h
        int d = t >> 2, h = t & 3;
        float s = 0.f;
#pragma unroll
        for (int m = 0; m < 64; m++) s += ws[h * 64 + m] * afs[m * 65 + d];
        aggs[t] = s;
    }
    __syncthreads();

    float v0a = 0.f, v1a = 0.f, v2a = 0.f, v3a = 0.f;
#pragma unroll 4
    for (int k = 0; k < 256; k += 4) {
        v0a += aggs[k] * wg[(size_t)k * 256 + t];
        v1a += aggs[k + 1] * wg[(size_t)(k + 1) * 256 + t];
        v2a += aggs[k + 2] * wg[(size_t)(k + 2) * 256 + t];
        v3a += aggs[k + 3] * wg[(size_t)(k + 3) * 256 + t];
    }
    float v = (v0a + v1a) + (v2a + v3a) + bg[t];
    v = fmaxf(v, 0.f);

    float s = warp_sum(v), q = warp_sum(v * v);
    if (lane == 0) { red[wid] = s; red[8 + wid] = q; }
    __syncthreads();
    if (t < 32) {
        float a = (lane < 8) ? red[lane] : 0.f;
        float b = (lane < 8) ? red[8 + lane] : 0.f;
#pragma unroll
        for (int o = 4; o; o >>= 1) {
            a += __shfl_xor_sync(0xffffffffu, a, o);
            b += __shfl_xor_sync(0xffffffffu, b, o);
        }
        if (lane == 0) { red[0] = a; red[8] = b; }
    }
    __syncthreads();
    float mu = red[0] * (1.f / 256.f), var = red[8] * (1.f / 256.f) - mu * mu;
    float rstd = rsqrtf(var + EPS);
    float y = (v - mu) * rstd * gg[t] + beg[t];
    out[(size_t)n * 256 + t] = y;                 // x_out
    out[34078720ull + (size_t)n * 256 + t] = y;   // m (== x_out), after new_if
}

// ---------------- launch ----------------
extern "C" void kernel_launch(void* const* d_in, const int* in_sizes, int n_in,
                              void* d_out, int out_size) {
    const float* x = (const float*)d_in[0];
    const float* iff = (const float*)d_in[1];
    const int* mask = (const int*)d_in[2];
    const int* ai = (const int*)d_in[3];
    const int* aj = (const int*)d_in[4];
    const float* w1 = (const float*)d_in[5], *b1 = (const float*)d_in[6];
    const float* g1 = (const float*)d_in[7], *be1 = (const float*)d_in[8];
    const float* w2 = (const float*)d_in[9], *b2 = (const float*)d_in[10];
    const float* g2 = (const float*)d_in[11], *be2 = (const float*)d_in[12];
    const float* wpre = (const float*)d_in[13], *bpre = (const float*)d_in[14];
    const float* watt = (const float*)d_in[15], *batt = (const float*)d_in[16];
    const float* gatt = (const float*)d_in[17], *beatt = (const float*)d_in[18];
    const float* wif = (const float*)d_in[19], *bif = (const float*)d_in[20];
    const float* gif = (const float*)d_in[21], *beif = (const float*)d_in[22];
    const float* wg = (const float*)d_in[23], *bg = (const float*)d_in[24];
    const float* gg = (const float*)d_in[25], *beg = (const float*)d_in[26];
    float* out = (float*)d_out;

    const int PS = (256 * 65 + 32 * 65) * 4;
    const int BS = (64 * 577 + 256 * 65 + 32 * 65) * 4 + 128 * 4;
    cudaFuncSetAttribute(p_kernel, cudaFuncAttributeMaxDynamicSharedMemorySize, PS);
    cudaFuncSetAttribute(big_kernel, cudaFuncAttributeMaxDynamicSharedMemorySize, BS);

    pack_kernel<<<1728, 256>>>(w1, watt, wif, b1, batt, bif);
    p_kernel<<<dim3(32, 2), 256, PS>>>(x);
    big_kernel<<<2048, 256, BS>>>(iff, ai, aj, g1, be1, gatt, beatt, gif, beif,
                                  w2, b2, g2, be2, wpre, bpre, mask,
                                  out + 524288 /* new_if section */);
    final_kernel<<<2048, 256>>>(wg, bg, gg, beg, out);
}

// round 3
// speedup vs baseline: 1.3608x; 1.3608x over previous
#include <cuda_runtime.h>
#include <cstdint>
#include <cstddef>

#define NN 2048
#define EPS 1e-5f

// ---------------- scratch (device globals; allocation-free rule) ----------------
__device__ float g_Wcat[768 * 576];          // packed [w1 | watt | wif]
__device__ float g_bcat[576];                // packed [b1 | batt | bif]
__device__ float g_P[2 * NN * 576];          // Pi (part 0), Pj (part 1)

__device__ __forceinline__ float warp_sum(float v) {
#pragma unroll
    for (int o = 16; o; o >>= 1) v += __shfl_xor_sync(0xffffffffu, v, o);
    return v;
}
__device__ __forceinline__ float warp_max(float v) {
#pragma unroll
    for (int o = 16; o; o >>= 1) v = fmaxf(v, __shfl_xor_sync(0xffffffffu, v, o));
    return v;
}

// swizzled index into ash: k-major, 64 floats/row, 4-float blocks XOR-swizzled by k
__device__ __forceinline__ int swz(int k, int row) {
    return (k << 6) + ((row & 60) ^ ((k << 2) & 60)) + (row & 3);
}

// scalar 4x4 micro (p_kernel only)
__device__ __forceinline__ void micro_fma32(const float* __restrict__ ap,
                                            const float* __restrict__ bp,
                                            float acc[4][4]) {
#pragma unroll 8
    for (int k = 0; k < 32; k++) {
        const float* apk = ap + k * 65;
        const float* bpk = bp + k * 65;
        float a0 = apk[0], a1 = apk[1], a2 = apk[2], a3 = apk[3];
        float b0 = bpk[0], b1 = bpk[1], b2 = bpk[2], b3 = bpk[3];
        acc[0][0] += a0 * b0; acc[0][1] += a0 * b1; acc[0][2] += a0 * b2; acc[0][3] += a0 * b3;
        acc[1][0] += a1 * b0; acc[1][1] += a1 * b1; acc[1][2] += a1 * b2; acc[1][3] += a1 * b3;
        acc[2][0] += a2 * b0; acc[2][1] += a2 * b1; acc[2][2] += a2 * b2; acc[2][3] += a2 * b3;
        acc[3][0] += a3 * b0; acc[3][1] += a3 * b1; acc[3][2] += a3 * b2; acc[3][3] += a3 * b3;
    }
}

// packed f32x2 micro: 32 k-steps, 4x4 tile as 8 fma.rn.f32x2 per k.
// abase: shared byte addr of ash + (kbase<<8)   (kbase multiple of 32)
// bbase: shared byte addr of weight panel (+ tx*16)
// ty16 : byte offset of this thread's 4-row block within a 64-row group
__device__ __forceinline__ void micro32x2(unsigned abase, unsigned bbase, int ty16,
                                          unsigned long long acc[4][2]) {
#pragma unroll
    for (int k = 0; k < 32; k++) {
        unsigned aaddr = abase + (unsigned)(k << 8) + (unsigned)(ty16 ^ ((k << 4) & 240));
        unsigned long long a01, a23;
        asm("ld.shared.v2.b64 {%0,%1}, [%2];" : "=l"(a01), "=l"(a23) : "r"(aaddr));
        float b0, b1, b2, b3;
        asm("ld.shared.v4.b32 {%0,%1,%2,%3}, [%4];"
            : "=f"(b0), "=f"(b1), "=f"(b2), "=f"(b3)
            : "r"(bbase + (unsigned)(k * 272)));
        unsigned long long B0, B1, B2, B3;
        asm("mov.b64 %0, {%1,%2};" : "=l"(B0) : "f"(b0), "f"(b0));
        asm("mov.b64 %0, {%1,%2};" : "=l"(B1) : "f"(b1), "f"(b1));
        asm("mov.b64 %0, {%1,%2};" : "=l"(B2) : "f"(b2), "f"(b2));
        asm("mov.b64 %0, {%1,%2};" : "=l"(B3) : "f"(b3), "f"(b3));
        asm("fma.rn.f32x2 %0, %1, %2, %0;" : "+l"(acc[0][0]) : "l"(a01), "l"(B0));
        asm("fma.rn.f32x2 %0, %1, %2, %0;" : "+l"(acc[0][1]) : "l"(a23), "l"(B0));
        asm("fma.rn.f32x2 %0, %1, %2, %0;" : "+l"(acc[1][0]) : "l"(a01), "l"(B1));
        asm("fma.rn.f32x2 %0, %1, %2, %0;" : "+l"(acc[1][1]) : "l"(a23), "l"(B1));
        asm("fma.rn.f32x2 %0, %1, %2, %0;" : "+l"(acc[2][0]) : "l"(a01), "l"(B2));
        asm("fma.rn.f32x2 %0, %1, %2, %0;" : "+l"(acc[2][1]) : "l"(a23), "l"(B2));
        asm("fma.rn.f32x2 %0, %1, %2, %0;" : "+l"(acc[3][0]) : "l"(a01), "l"(B3));
        asm("fma.rn.f32x2 %0, %1, %2, %0;" : "+l"(acc[3][1]) : "l"(a23), "l"(B3));
    }
}

// ---------------- K0: pack weights ----------------
__global__ void pack_kernel(const float* __restrict__ w1, const float* __restrict__ watt,
                            const float* __restrict__ wif, const float* __restrict__ b1,
                            const float* __restrict__ batt, const float* __restrict__ bif) {
    int idx = blockIdx.x * blockDim.x + threadIdx.x;
    if (idx < 768 * 576) {
        int r = idx / 576, c = idx - r * 576;
        float v = (c < 256) ? w1[r * 256 + c]
                 : (c < 320) ? watt[r * 64 + (c - 256)]
                             : wif[r * 256 + (c - 320)];
        g_Wcat[idx] = v;
    }
    if (idx < 576) {
        g_bcat[idx] = (idx < 256) ? b1[idx] : (idx < 320) ? batt[idx - 256] : bif[idx - 320];
    }
}

// ---------------- K1: P = x @ Wcat(part) ----------------
__global__ void __launch_bounds__(256) p_kernel(const float* __restrict__ x) {
    extern __shared__ float sm[];
    float* xs = sm;               // [256][65] transposed x tile
    float* wsh = xs + 256 * 65;   // [32][65]

    int nb = blockIdx.x, part = blockIdx.y;
    int t = threadIdx.x, ty = t >> 4, tx = t & 15;

    {
        int row = t >> 2, k0 = (t & 3) * 64;
        const float* src = x + (size_t)(nb * 64 + row) * 256 + k0;
#pragma unroll
        for (int k = 0; k < 64; k += 4) {
            float4 v = *(const float4*)(src + k);
            xs[(k0 + k) * 65 + row] = v.x; xs[(k0 + k + 1) * 65 + row] = v.y;
            xs[(k0 + k + 2) * 65 + row] = v.z; xs[(k0 + k + 3) * 65 + row] = v.w;
        }
    }
    __syncthreads();

    for (int cc = 0; cc < 9; cc++) {
        float acc[4][4] = {};
        for (int kp = 0; kp < 8; kp++) {
            {
                int k = t >> 3, cb = (t & 7) * 8;
                const float* src = g_Wcat + (size_t)(part * 256 + kp * 32 + k) * 576 + cc * 64 + cb;
                float4 v0 = *(const float4*)src, v1 = *(const float4*)(src + 4);
                float* d = wsh + k * 65 + cb;
                d[0] = v0.x; d[1] = v0.y; d[2] = v0.z; d[3] = v0.w;
                d[4] = v1.x; d[5] = v1.y; d[6] = v1.z; d[7] = v1.w;
            }
            __syncthreads();
            micro_fma32(xs + kp * 32 * 65 + ty * 4, wsh + tx * 4, acc);
            __syncthreads();
        }
#pragma unroll
        for (int ri = 0; ri < 4; ri++) {
            float4 v = make_float4(acc[ri][0], acc[ri][1], acc[ri][2], acc[ri][3]);
            *(float4*)(g_P + (size_t)part * NN * 576 +
                       (size_t)(nb * 64 + ty * 4 + ri) * 576 + cc * 64 + tx * 4) = v;
        }
    }
}

// ---------------- K2: fully fused per-n kernel ----------------
__global__ void __launch_bounds__(256) big_kernel(
    const float* __restrict__ IF, const int* __restrict__ ai, const int* __restrict__ aj,
    const float* __restrict__ g1, const float* __restrict__ be1,
    const float* __restrict__ gatt, const float* __restrict__ beatt,
    const float* __restrict__ gif, const float* __restrict__ beif,
    const float* __restrict__ w2, const float* __restrict__ b2,
    const float* __restrict__ g2, const float* __restrict__ be2,
    const float* __restrict__ wpre, const float* __restrict__ bpre,
    const int* __restrict__ mask,
    const float* __restrict__ wg, const float* __restrict__ bg,
    const float* __restrict__ gg, const float* __restrict__ beg,
    float* __restrict__ out) {
    extern __shared__ float sm[];
    float* tbuf = sm;                          // [64][576]
    float* ash  = sm + 36864;                  // [256][64] swizzled: IF^T, then h1^T
    float* wsh  = sm + 36864 + 16384;          // 2 x [32][68] weight panels
    int*   idxs = (int*)(sm + 36864 + 16384 + 4352);  // 128 ints
    // aliases in dead tbuf regions (cols 0..255 of rows 0..3 are free after phase 2)
    float* wsm  = tbuf;            // [4][64] softmax weights
    float* slog = tbuf + 576;      // [64][4] logits
    float* aggs = tbuf + 1152;     // [256]
    float* red  = tbuf + 1728;     // [16]

    const int n = blockIdx.x, t = threadIdx.x;
    const int lane = t & 31, wid = t >> 5;
    const int ty4 = (t >> 4) << 2, tx4 = (t & 15) << 2;
    const int ty16 = ty4 << 2;
    const unsigned tx16 = (unsigned)(tx4 << 2);
    const int wk = t >> 3, wc = (t & 7) * 8;
    const float NEG = __int_as_float(0xff800000);
    const unsigned asho = (unsigned)__cvta_generic_to_shared(ash);
    const unsigned wsho = (unsigned)__cvta_generic_to_shared(wsh);

    if (t < 64) { idxs[t] = ai[n * 64 + t]; idxs[64 + t] = aj[n * 64 + t]; }

    // load IF tile transposed + swizzled into ash
    {
        int row = t >> 2, k0 = (t & 3) * 64;
        const float* src = IF + (size_t)(n * 64 + row) * 256 + k0;
#pragma unroll 4
        for (int k = 0; k < 64; k += 4) {
            float4 v = *(const float4*)(src + k);
            ash[swz(k0 + k, row)]     = v.x;
            ash[swz(k0 + k + 1, row)] = v.y;
            ash[swz(k0 + k + 2, row)] = v.z;
            ash[swz(k0 + k + 3, row)] = v.w;
        }
    }

    // -------- Phase 1: t = IF @ Wf + Pi[i] + Pj[j] + bcat  (9 x 64-col tiles) --------
#pragma unroll 1
    for (int cc = 0; cc < 9; cc++) {
        const float* wsrc = g_Wcat + (size_t)512 * 576 + cc * 64;
        float4 r0 = *(const float4*)(wsrc + wk * 576 + wc);
        float4 r1 = *(const float4*)(wsrc + wk * 576 + wc + 4);
        *(float4*)(wsh + wk * 68 + wc) = r0;
        *(float4*)(wsh + wk * 68 + wc + 4) = r1;
        __syncthreads();
        unsigned long long acc[4][2] = {{0ull,0ull},{0ull,0ull},{0ull,0ull},{0ull,0ull}};
#pragma unroll 1
        for (int kp = 0; kp < 8; kp++) {
            if (kp < 7) {
                const float* s = wsrc + (size_t)(kp + 1) * 32 * 576 + wk * 576 + wc;
                r0 = *(const float4*)s; r1 = *(const float4*)(s + 4);
            }
            micro32x2(asho + (unsigned)((kp * 32) << 8),
                      wsho + (unsigned)((kp & 1) * 8704) + tx16, ty16, acc);
            if (kp < 7) {
                float* d = wsh + ((kp + 1) & 1) * 2176 + wk * 68 + wc;
                *(float4*)d = r0; *(float4*)(d + 4) = r1;
                __syncthreads();
            }
        }
        int c0 = cc * 64 + tx4;
        float4 bb = *(const float4*)(g_bcat + c0);
        float vals[4][4];
#pragma unroll
        for (int c = 0; c < 4; c++) {
            float lo, hi;
            asm("mov.b64 {%0,%1}, %2;" : "=f"(lo), "=f"(hi) : "l"(acc[c][0]));
            vals[0][c] = lo; vals[1][c] = hi;
            asm("mov.b64 {%0,%1}, %2;" : "=f"(lo), "=f"(hi) : "l"(acc[c][1]));
            vals[2][c] = lo; vals[3][c] = hi;
        }
#pragma unroll
        for (int ri = 0; ri < 4; ri++) {
            int r = ty4 + ri;
            const float4 pi = *(const float4*)(g_P + (size_t)idxs[r] * 576 + c0);
            const float4 pj = *(const float4*)(g_P + (size_t)NN * 576 + (size_t)idxs[64 + r] * 576 + c0);
            float4 o;
            o.x = vals[ri][0] + pi.x + pj.x + bb.x;
            o.y = vals[ri][1] + pi.y + pj.y + bb.y;
            o.z = vals[ri][2] + pi.z + pj.z + bb.z;
            o.w = vals[ri][3] + pi.w + pj.w + bb.w;
            *(float4*)(tbuf + (size_t)r * 576 + c0) = o;
        }
    }
    __syncthreads();

    // -------- Phase 2: relu + LayerNorm per segment --------
    const float inv256 = 1.0f / 256.0f, inv64 = 1.0f / 64.0f;
#pragma unroll 1
    for (int rr = 0; rr < 8; rr++) {
        int row = rr * 8 + wid;
        float* trow = tbuf + (size_t)row * 576;
        {   // seg1 -> h1 normalized, transposed+swizzled into ash
            float v[8], s = 0.f, q = 0.f;
#pragma unroll
            for (int j = 0; j < 8; j++) {
                float xv = fmaxf(trow[lane + j * 32], 0.f);
                v[j] = xv; s += xv; q += xv * xv;
            }
            s = warp_sum(s); q = warp_sum(q);
            float mu = s * inv256, rstd = rsqrtf(q * inv256 - mu * mu + EPS);
#pragma unroll
            for (int j = 0; j < 8; j++) {
                int c = lane + j * 32;
                ash[swz(c, row)] = (v[j] - mu) * rstd * g1[c] + be1[c];
            }
        }
        {   // seg2 -> att features, normalized IN PLACE (tbuf cols 256..319)
            float x0 = fmaxf(trow[256 + lane], 0.f), x1 = fmaxf(trow[288 + lane], 0.f);
            float s = warp_sum(x0 + x1), q = warp_sum(x0 * x0 + x1 * x1);
            float mu = s * inv64, rstd = rsqrtf(q * inv64 - mu * mu + EPS);
            trow[256 + lane] = (x0 - mu) * rstd * gatt[lane] + beatt[lane];
            trow[288 + lane] = (x1 - mu) * rstd * gatt[32 + lane] + beatt[32 + lane];
        }
        {   // seg3 -> new interaction features, straight to output
            float v[8], s = 0.f, q = 0.f;
#pragma unroll
            for (int j = 0; j < 8; j++) {
                float xv = fmaxf(trow[320 + lane + j * 32], 0.f);
                v[j] = xv; s += xv; q += xv * xv;
            }
            s = warp_sum(s); q = warp_sum(q);
            float mu = s * inv256, rstd = rsqrtf(q * inv256 - mu * mu + EPS);
            float* dst = out + 524288 + ((size_t)n * 64 + row) * 256;
#pragma unroll
            for (int j = 0; j < 8; j++) {
                int c = lane + j * 32;
                dst[c] = (v[j] - mu) * rstd * gif[c] + beif[c];
            }
        }
    }

    // -------- Phase 3: t2 = h1 @ w2 + b2  (4 x 64-col tiles into tbuf cols 320..575) --------
#pragma unroll 1
    for (int cc = 0; cc < 4; cc++) {
        const float* wsrc = w2 + cc * 64;
        float4 r0 = *(const float4*)(wsrc + wk * 256 + wc);
        float4 r1 = *(const float4*)(wsrc + wk * 256 + wc + 4);
        *(float4*)(wsh + wk * 68 + wc) = r0;
        *(float4*)(wsh + wk * 68 + wc + 4) = r1;
        __syncthreads();
        unsigned long long acc[4][2] = {{0ull,0ull},{0ull,0ull},{0ull,0ull},{0ull,0ull}};
#pragma unroll 1
        for (int kp = 0; kp < 8; kp++) {
            if (kp < 7) {
                const float* s = wsrc + (size_t)(kp + 1) * 32 * 256 + wk * 256 + wc;
                r0 = *(const float4*)s; r1 = *(const float4*)(s + 4);
            }
            micro32x2(asho + (unsigned)((kp * 32) << 8),
                      wsho + (unsigned)((kp & 1) * 8704) + tx16, ty16, acc);
            if (kp < 7) {
                float* d = wsh + ((kp + 1) & 1) * 2176 + wk * 68 + wc;
                *(float4*)d = r0; *(float4*)(d + 4) = r1;
                __syncthreads();
            }
        }
        int c0 = cc * 64 + tx4;
        float4 bb = *(const float4*)(b2 + c0);
        float vals[4][4];
#pragma unroll
        for (int c = 0; c < 4; c++) {
            float lo, hi;
            asm("mov.b64 {%0,%1}, %2;" : "=f"(lo), "=f"(hi) : "l"(acc[c][0]));
            vals[0][c] = lo; vals[1][c] = hi;
            asm("mov.b64 {%0,%1}, %2;" : "=f"(lo), "=f"(hi) : "l"(acc[c][1]));
            vals[2][c] = lo; vals[3][c] = hi;
        }
#pragma unroll
        for (int ri = 0; ri < 4; ri++) {
            int r = ty4 + ri;
            float4 o;
            o.x = vals[ri][0] + bb.x; o.y = vals[ri][1] + bb.y;
            o.z = vals[ri][2] + bb.z; o.w = vals[ri][3] + bb.w;
            *(float4*)(tbuf + (size_t)r * 576 + 320 + c0) = o;
        }
    }
    __syncthreads();

    // -------- Phase 4: h2 = LN(relu(t2)); logits -> slog --------
#pragma unroll 1
    for (int rr = 0; rr < 8; rr++) {
        int row = rr * 8 + wid;
        const float* trow = tbuf + (size_t)row * 576 + 320;
        float v[8], s = 0.f, q = 0.f;
#pragma unroll
        for (int j = 0; j < 8; j++) {
            float xv = fmaxf(trow[lane + j * 32], 0.f);
            v[j] = xv; s += xv; q += xv * xv;
        }
        s = warp_sum(s); q = warp_sum(q);
        float mu = s * inv256, rstd = rsqrtf(q * inv256 - mu * mu + EPS);
        float l0 = 0.f, l1 = 0.f, l2 = 0.f, l3 = 0.f;
#pragma unroll
        for (int j = 0; j < 8; j++) {
            int c = lane + j * 32;
            float y = (v[j] - mu) * rstd * g2[c] + be2[c];
            float4 wp = *(const float4*)(wpre + (size_t)c * 4);
            l0 += y * wp.x; l1 += y * wp.y; l2 += y * wp.z; l3 += y * wp.w;
        }
        l0 = warp_sum(l0); l1 = warp_sum(l1); l2 = warp_sum(l2); l3 = warp_sum(l3);
        if (lane == 0) {
            bool mk = mask[n * 64 + row] != 0;
            slog[row * 4 + 0] = mk ? NEG : (l0 + bpre[0]);
            slog[row * 4 + 1] = mk ? NEG : (l1 + bpre[1]);
            slog[row * 4 + 2] = mk ? NEG : (l2 + bpre[2]);
            slog[row * 4 + 3] = mk ? NEG : (l3 + bpre[3]);
        }
    }
    __syncthreads();

    // -------- Phase 5: per-head top-16 softmax -> wsm --------
    if (wid < 4) {
        int h = wid;
        float v0 = slog[lane * 4 + h], v1 = slog[(32 + lane) * 4 + h];
        float c0 = v0, c1 = v1;
        float thr = NEG, maxv = NEG;
#pragma unroll 1
        for (int it = 0; it < 16; it++) {
            float loc = fmaxf(c0, c1);
            float m = warp_max(loc);
            if (it == 0) maxv = m;
            if (m == NEG) break;
            thr = m;
            unsigned bl = __ballot_sync(0xffffffffu, loc == m);
            int src = __ffs(bl) - 1;
            if (lane == src) { if (c0 == m) c0 = NEG; else c1 = NEG; }
        }
        float e0 = (v0 >= thr) ? expf(v0 - maxv) : 0.f;
        float e1 = (v1 >= thr) ? expf(v1 - maxv) : 0.f;
        float inv = 1.f / warp_sum(e0 + e1);
        wsm[h * 64 + lane] = e0 * inv;
        wsm[h * 64 + 32 + lane] = e1 * inv;
    }
    __syncthreads();

    // -------- Phase 6: agg[d,h] = sum_m w[h,m] * af[m,d]  (af in tbuf cols 256..319) --------
    {
        int d = t >> 2, h = t & 3;
        float s = 0.f;
#pragma unroll
        for (int m = 0; m < 64; m++) s += wsm[h * 64 + m] * tbuf[(size_t)m * 576 + 256 + d];
        aggs[t] = s;
    }
    __syncthreads();

    // -------- Phase 7: x_out = LN(relu(agg @ wg + bg)) --------
    {
        float v0a = 0.f, v1a = 0.f, v2a = 0.f, v3a = 0.f;
#pragma unroll 4
        for (int k = 0; k < 256; k += 4) {
            v0a += aggs[k]     * wg[(size_t)k * 256 + t];
            v1a += aggs[k + 1] * wg[(size_t)(k + 1) * 256 + t];
            v2a += aggs[k + 2] * wg[(size_t)(k + 2) * 256 + t];
            v3a += aggs[k + 3] * wg[(size_t)(k + 3) * 256 + t];
        }
        float v = fmaxf((v0a + v1a) + (v2a + v3a) + bg[t], 0.f);
        float s = warp_sum(v), q = warp_sum(v * v);
        if (lane == 0) { red[wid] = s; red[8 + wid] = q; }
        __syncthreads();
        if (t < 32) {
            float a = (lane < 8) ? red[lane] : 0.f;
            float b = (lane < 8) ? red[8 + lane] : 0.f;
#pragma unroll
            for (int o = 4; o; o >>= 1) {
                a += __shfl_xor_sync(0xffffffffu, a, o);
                b += __shfl_xor_sync(0xffffffffu, b, o);
            }
            if (lane == 0) { red[0] = a; red[8] = b; }
        }
        __syncthreads();
        float mu = red[0] * (1.f / 256.f), rstd = rsqrtf(red[8] * (1.f / 256.f) - mu * mu + EPS);
        float y = (v - mu) * rstd * gg[t] + beg[t];
        out[(size_t)n * 256 + t] = y;                 // x_out
        out[34078720ull + (size_t)n * 256 + t] = y;   // m (== x_out)
    }
}

// ---------------- launch ----------------
extern "C" void kernel_launch(void* const* d_in, const int* in_sizes, int n_in,
                              void* d_out, int out_size) {
    const float* x = (const float*)d_in[0];
    const float* iff = (const float*)d_in[1];
    const int* mask = (const int*)d_in[2];
    const int* ai = (const int*)d_in[3];
    const int* aj = (const int*)d_in[4];
    const float* w1 = (const float*)d_in[5], *b1 = (const float*)d_in[6];
    const float* g1 = (const float*)d_in[7], *be1 = (const float*)d_in[8];
    const float* w2 = (const float*)d_in[9], *b2 = (const float*)d_in[10];
    const float* g2 = (const float*)d_in[11], *be2 = (const float*)d_in[12];
    const float* wpre = (const float*)d_in[13], *bpre = (const float*)d_in[14];
    const float* watt = (const float*)d_in[15], *batt = (const float*)d_in[16];
    const float* gatt = (const float*)d_in[17], *beatt = (const float*)d_in[18];
    const float* wif = (const float*)d_in[19], *bif = (const float*)d_in[20];
    const float* gif = (const float*)d_in[21], *beif = (const float*)d_in[22];
    const float* wg = (const float*)d_in[23], *bg = (const float*)d_in[24];
    const float* gg = (const float*)d_in[25], *beg = (const float*)d_in[26];
    float* out = (float*)d_out;

    const int PS = (256 * 65 + 32 * 65) * 4;
    const int BS = (36864 + 16384 + 4352) * 4 + 128 * 4;  // 230,912 B
    cudaFuncSetAttribute(p_kernel, cudaFuncAttributeMaxDynamicSharedMemorySize, PS);
    cudaFuncSetAttribute(big_kernel, cudaFuncAttributeMaxDynamicSharedMemorySize, BS);

    pack_kernel<<<1728, 256>>>(w1, watt, wif, b1, batt, bif);
    p_kernel<<<dim3(32, 2), 256, PS>>>(x);
    big_kernel<<<2048, 256, BS>>>(iff, ai, aj, g1, be1, gatt, beatt, gif, beif,
                                  w2, b2, g2, be2, wpre, bpre, mask,
                                  wg, bg, gg, beg, out);
}

// round 4
// speedup vs baseline: 1.3634x; 1.0019x over previous
#include <cuda_runtime.h>
#include <cstdint>
#include <cstddef>

#define NN 2048
#define EPS 1e-5f

// ---------------- scratch (device globals; allocation-free rule) ----------------
__device__ float g_Wcat[768 * 576];          // packed [w1 | watt | wif]
__device__ float g_bcat[576];                // packed [b1 | batt | bif]
__device__ float g_P[2 * NN * 576];          // Pi (part 0), Pj (part 1)

__device__ __forceinline__ float warp_sum(float v) {
#pragma unroll
    for (int o = 16; o; o >>= 1) v += __shfl_xor_sync(0xffffffffu, v, o);
    return v;
}
__device__ __forceinline__ float warp_max(float v) {
#pragma unroll
    for (int o = 16; o; o >>= 1) v = fmaxf(v, __shfl_xor_sync(0xffffffffu, v, o));
    return v;
}

// swizzled index into ash: k-major, 64 floats/row, 4-float blocks XOR-swizzled by k
__device__ __forceinline__ int swz(int k, int row) {
    return (k << 6) + ((row & 60) ^ ((k << 2) & 60)) + (row & 3);
}

// scalar 4x4 micro (p_kernel only)
__device__ __forceinline__ void micro_fma32(const float* __restrict__ ap,
                                            const float* __restrict__ bp,
                                            float acc[4][4]) {
#pragma unroll 8
    for (int k = 0; k < 32; k++) {
        const float* apk = ap + k * 65;
        const float* bpk = bp + k * 65;
        float a0 = apk[0], a1 = apk[1], a2 = apk[2], a3 = apk[3];
        float b0 = bpk[0], b1 = bpk[1], b2 = bpk[2], b3 = bpk[3];
        acc[0][0] += a0 * b0; acc[0][1] += a0 * b1; acc[0][2] += a0 * b2; acc[0][3] += a0 * b3;
        acc[1][0] += a1 * b0; acc[1][1] += a1 * b1; acc[1][2] += a1 * b2; acc[1][3] += a1 * b3;
        acc[2][0] += a2 * b0; acc[2][1] += a2 * b1; acc[2][2] += a2 * b2; acc[2][3] += a2 * b3;
        acc[3][0] += a3 * b0; acc[3][1] += a3 * b1; acc[3][2] += a3 * b2; acc[3][3] += a3 * b3;
    }
}

// packed f32x2 micro: 32 k-steps, 4x4 tile as 8 fma.rn.f32x2 per k.
// abase: shared byte addr of ash + (kbase<<8)   (kbase multiple of 32)
// bbase: shared byte addr of weight panel (+ tx*16)
// ty16 : byte offset of this thread's 4-row block within a 64-row group
__device__ __forceinline__ void micro32x2(unsigned abase, unsigned bbase, int ty16,
                                          unsigned long long acc[4][2]) {
#pragma unroll
    for (int k = 0; k < 32; k++) {
        unsigned aaddr = abase + (unsigned)(k << 8) + (unsigned)(ty16 ^ ((k << 4) & 240));
        unsigned long long a01, a23;
        asm("ld.shared.v2.b64 {%0,%1}, [%2];" : "=l"(a01), "=l"(a23) : "r"(aaddr));
        float b0, b1, b2, b3;
        asm("ld.shared.v4.b32 {%0,%1,%2,%3}, [%4];"
            : "=f"(b0), "=f"(b1), "=f"(b2), "=f"(b3)
            : "r"(bbase + (unsigned)(k * 272)));
        unsigned long long B0, B1, B2, B3;
        asm("mov.b64 %0, {%1,%2};" : "=l"(B0) : "f"(b0), "f"(b0));
        asm("mov.b64 %0, {%1,%2};" : "=l"(B1) : "f"(b1), "f"(b1));
        asm("mov.b64 %0, {%1,%2};" : "=l"(B2) : "f"(b2), "f"(b2));
        asm("mov.b64 %0, {%1,%2};" : "=l"(B3) : "f"(b3), "f"(b3));
        asm("fma.rn.f32x2 %0, %1, %2, %0;" : "+l"(acc[0][0]) : "l"(a01), "l"(B0));
        asm("fma.rn.f32x2 %0, %1, %2, %0;" : "+l"(acc[0][1]) : "l"(a23), "l"(B0));
        asm("fma.rn.f32x2 %0, %1, %2, %0;" : "+l"(acc[1][0]) : "l"(a01), "l"(B1));
        asm("fma.rn.f32x2 %0, %1, %2, %0;" : "+l"(acc[1][1]) : "l"(a23), "l"(B1));
        asm("fma.rn.f32x2 %0, %1, %2, %0;" : "+l"(acc[2][0]) : "l"(a01), "l"(B2));
        asm("fma.rn.f32x2 %0, %1, %2, %0;" : "+l"(acc[2][1]) : "l"(a23), "l"(B2));
        asm("fma.rn.f32x2 %0, %1, %2, %0;" : "+l"(acc[3][0]) : "l"(a01), "l"(B3));
        asm("fma.rn.f32x2 %0, %1, %2, %0;" : "+l"(acc[3][1]) : "l"(a23), "l"(B3));
    }
}

// ---------------- K0: pack weights ----------------
__global__ void pack_kernel(const float* __restrict__ w1, const float* __restrict__ watt,
                            const float* __restrict__ wif, const float* __restrict__ b1,
                            const float* __restrict__ batt, const float* __restrict__ bif) {
    int idx = blockIdx.x * blockDim.x + threadIdx.x;
    if (idx < 768 * 576) {
        int r = idx / 576, c = idx - r * 576;
        float v = (c < 256) ? w1[r * 256 + c]
                 : (c < 320) ? watt[r * 64 + (c - 256)]
                             : wif[r * 256 + (c - 320)];
        g_Wcat[idx] = v;
    }
    if (idx < 576) {
        g_bcat[idx] = (idx < 256) ? b1[idx] : (idx < 320) ? batt[idx - 256] : bif[idx - 320];
    }
}

// ---------------- K1: P = x @ Wcat(part) ----------------
__global__ void __launch_bounds__(256) p_kernel(const float* __restrict__ x) {
    extern __shared__ float sm[];
    float* xs = sm;               // [256][65] transposed x tile
    float* wsh = xs + 256 * 65;   // [32][65]

    int nb = blockIdx.x, part = blockIdx.y;
    int t = threadIdx.x, ty = t >> 4, tx = t & 15;

    {
        int row = t >> 2, k0 = (t & 3) * 64;
        const float* src = x + (size_t)(nb * 64 + row) * 256 + k0;
#pragma unroll
        for (int k = 0; k < 64; k += 4) {
            float4 v = *(const float4*)(src + k);
            xs[(k0 + k) * 65 + row] = v.x; xs[(k0 + k + 1) * 65 + row] = v.y;
            xs[(k0 + k + 2) * 65 + row] = v.z; xs[(k0 + k + 3) * 65 + row] = v.w;
        }
    }
    __syncthreads();

    for (int cc = 0; cc < 9; cc++) {
        float acc[4][4] = {};
        for (int kp = 0; kp < 8; kp++) {
            {
                int k = t >> 3, cb = (t & 7) * 8;
                const float* src = g_Wcat + (size_t)(part * 256 + kp * 32 + k) * 576 + cc * 64 + cb;
                float4 v0 = *(const float4*)src, v1 = *(const float4*)(src + 4);
                float* d = wsh + k * 65 + cb;
                d[0] = v0.x; d[1] = v0.y; d[2] = v0.z; d[3] = v0.w;
                d[4] = v1.x; d[5] = v1.y; d[6] = v1.z; d[7] = v1.w;
            }
            __syncthreads();
            micro_fma32(xs + kp * 32 * 65 + ty * 4, wsh + tx * 4, acc);
            __syncthreads();
        }
#pragma unroll
        for (int ri = 0; ri < 4; ri++) {
            float4 v = make_float4(acc[ri][0], acc[ri][1], acc[ri][2], acc[ri][3]);
            *(float4*)(g_P + (size_t)part * NN * 576 +
                       (size_t)(nb * 64 + ty * 4 + ri) * 576 + cc * 64 + tx * 4) = v;
        }
    }
}

// ---------------- K2: fully fused per-n kernel ----------------
__global__ void __launch_bounds__(256) big_kernel(
    const float* __restrict__ IF, const int* __restrict__ ai, const int* __restrict__ aj,
    const float* __restrict__ g1, const float* __restrict__ be1,
    const float* __restrict__ gatt, const float* __restrict__ beatt,
    const float* __restrict__ gif, const float* __restrict__ beif,
    const float* __restrict__ w2, const float* __restrict__ b2,
    const float* __restrict__ g2, const float* __restrict__ be2,
    const float* __restrict__ wpre, const float* __restrict__ bpre,
    const int* __restrict__ mask,
    const float* __restrict__ wg, const float* __restrict__ bg,
    const float* __restrict__ gg, const float* __restrict__ beg,
    float* __restrict__ out) {
    extern __shared__ float sm[];
    float* tbuf = sm;                          // [64][576]
    float* ash  = sm + 36864;                  // [256][64] swizzled: IF^T, then h1^T
    float* wsh  = sm + 36864 + 16384;          // 2 x [32][68] weight panels
    int*   idxs = (int*)(sm + 36864 + 16384 + 4352);  // 128 ints
    // aliases in dead tbuf regions (cols 0..255 of rows 0..3 are free after phase 2)
    float* wsm  = tbuf;            // [4][64] softmax weights
    float* slog = tbuf + 576;      // [64][4] logits
    float* aggs = tbuf + 1152;     // [256]
    float* red  = tbuf + 1728;     // [16]

    const int n = blockIdx.x, t = threadIdx.x;
    const int lane = t & 31, wid = t >> 5;
    const int ty4 = (t >> 4) << 2, tx4 = (t & 15) << 2;
    const int ty16 = ty4 << 2;
    const unsigned tx16 = (unsigned)(tx4 << 2);
    const int wk = t >> 3, wc = (t & 7) * 8;
    const float NEG = __int_as_float(0xff800000);
    const unsigned asho = (unsigned)__cvta_generic_to_shared(ash);
    const unsigned wsho = (unsigned)__cvta_generic_to_shared(wsh);

    if (t < 64) { idxs[t] = ai[n * 64 + t]; idxs[64 + t] = aj[n * 64 + t]; }

    // load IF tile transposed + swizzled into ash
    {
        int row = t >> 2, k0 = (t & 3) * 64;
        const float* src = IF + (size_t)(n * 64 + row) * 256 + k0;
#pragma unroll 4
        for (int k = 0; k < 64; k += 4) {
            float4 v = *(const float4*)(src + k);
            ash[swz(k0 + k, row)]     = v.x;
            ash[swz(k0 + k + 1, row)] = v.y;
            ash[swz(k0 + k + 2, row)] = v.z;
            ash[swz(k0 + k + 3, row)] = v.w;
        }
    }

    // -------- Phase 1: t = IF @ Wf + Pi[i] + Pj[j] + bcat  (9 x 64-col tiles) --------
#pragma unroll 1
    for (int cc = 0; cc < 9; cc++) {
        const float* wsrc = g_Wcat + (size_t)512 * 576 + cc * 64;
        float4 r0 = *(const float4*)(wsrc + wk * 576 + wc);
        float4 r1 = *(const float4*)(wsrc + wk * 576 + wc + 4);
        *(float4*)(wsh + wk * 68 + wc) = r0;
        *(float4*)(wsh + wk * 68 + wc + 4) = r1;
        __syncthreads();
        unsigned long long acc[4][2] = {{0ull,0ull},{0ull,0ull},{0ull,0ull},{0ull,0ull}};
#pragma unroll 1
        for (int kp = 0; kp < 8; kp++) {
            if (kp < 7) {
                const float* s = wsrc + (size_t)(kp + 1) * 32 * 576 + wk * 576 + wc;
                r0 = *(const float4*)s; r1 = *(const float4*)(s + 4);
            }
            micro32x2(asho + (unsigned)((kp * 32) << 8),
                      wsho + (unsigned)((kp & 1) * 8704) + tx16, ty16, acc);
            if (kp < 7) {
                float* d = wsh + ((kp + 1) & 1) * 2176 + wk * 68 + wc;
                *(float4*)d = r0; *(float4*)(d + 4) = r1;
                __syncthreads();
            }
        }
        int c0 = cc * 64 + tx4;
        float4 bb = *(const float4*)(g_bcat + c0);
        float vals[4][4];
#pragma unroll
        for (int c = 0; c < 4; c++) {
            float lo, hi;
            asm("mov.b64 {%0,%1}, %2;" : "=f"(lo), "=f"(hi) : "l"(acc[c][0]));
            vals[0][c] = lo; vals[1][c] = hi;
            asm("mov.b64 {%0,%1}, %2;" : "=f"(lo), "=f"(hi) : "l"(acc[c][1]));
            vals[2][c] = lo; vals[3][c] = hi;
        }
#pragma unroll
        for (int ri = 0; ri < 4; ri++) {
            int r = ty4 + ri;
            const float4 pi = *(const float4*)(g_P + (size_t)idxs[r] * 576 + c0);
            const float4 pj = *(const float4*)(g_P + (size_t)NN * 576 + (size_t)idxs[64 + r] * 576 + c0);
            float4 o;
            o.x = vals[ri][0] + pi.x + pj.x + bb.x;
            o.y = vals[ri][1] + pi.y + pj.y + bb.y;
            o.z = vals[ri][2] + pi.z + pj.z + bb.z;
            o.w = vals[ri][3] + pi.w + pj.w + bb.w;
            *(float4*)(tbuf + (size_t)r * 576 + c0) = o;
        }
    }
    __syncthreads();

    // -------- Phase 2: relu + LayerNorm per segment --------
    const float inv256 = 1.0f / 256.0f, inv64 = 1.0f / 64.0f;
#pragma unroll 1
    for (int rr = 0; rr < 8; rr++) {
        int row = rr * 8 + wid;
        float* trow = tbuf + (size_t)row * 576;
        {   // seg1 -> h1 normalized, transposed+swizzled into ash
            float v[8], s = 0.f, q = 0.f;
#pragma unroll
            for (int j = 0; j < 8; j++) {
                float xv = fmaxf(trow[lane + j * 32], 0.f);
                v[j] = xv; s += xv; q += xv * xv;
            }
            s = warp_sum(s); q = warp_sum(q);
            float mu = s * inv256, rstd = rsqrtf(q * inv256 - mu * mu + EPS);
#pragma unroll
            for (int j = 0; j < 8; j++) {
                int c = lane + j * 32;
                ash[swz(c, row)] = (v[j] - mu) * rstd * g1[c] + be1[c];
            }
        }
        {   // seg2 -> att features, normalized IN PLACE (tbuf cols 256..319)
            float x0 = fmaxf(trow[256 + lane], 0.f), x1 = fmaxf(trow[288 + lane], 0.f);
            float s = warp_sum(x0 + x1), q = warp_sum(x0 * x0 + x1 * x1);
            float mu = s * inv64, rstd = rsqrtf(q * inv64 - mu * mu + EPS);
            trow[256 + lane] = (x0 - mu) * rstd * gatt[lane] + beatt[lane];
            trow[288 + lane] = (x1 - mu) * rstd * gatt[32 + lane] + beatt[32 + lane];
        }
        {   // seg3 -> new interaction features, straight to output
            float v[8], s = 0.f, q = 0.f;
#pragma unroll
            for (int j = 0; j < 8; j++) {
                float xv = fmaxf(trow[320 + lane + j * 32], 0.f);
                v[j] = xv; s += xv; q += xv * xv;
            }
            s = warp_sum(s); q = warp_sum(q);
            float mu = s * inv256, rstd = rsqrtf(q * inv256 - mu * mu + EPS);
            float* dst = out + 524288 + ((size_t)n * 64 + row) * 256;
#pragma unroll
            for (int j = 0; j < 8; j++) {
                int c = lane + j * 32;
                dst[c] = (v[j] - mu) * rstd * gif[c] + beif[c];
            }
        }
    }

    // -------- Phase 3: t2 = h1 @ w2 + b2  (4 x 64-col tiles into tbuf cols 320..575) --------
#pragma unroll 1
    for (int cc = 0; cc < 4; cc++) {
        const float* wsrc = w2 + cc * 64;
        float4 r0 = *(const float4*)(wsrc + wk * 256 + wc);
        float4 r1 = *(const float4*)(wsrc + wk * 256 + wc + 4);
        *(float4*)(wsh + wk * 68 + wc) = r0;
        *(float4*)(wsh + wk * 68 + wc + 4) = r1;
        __syncthreads();
        unsigned long long acc[4][2] = {{0ull,0ull},{0ull,0ull},{0ull,0ull},{0ull,0ull}};
#pragma unroll 1
        for (int kp = 0; kp < 8; kp++) {
            if (kp < 7) {
                const float* s = wsrc + (size_t)(kp + 1) * 32 * 256 + wk * 256 + wc;
                r0 = *(const float4*)s; r1 = *(const float4*)(s + 4);
            }
            micro32x2(asho + (unsigned)((kp * 32) << 8),
                      wsho + (unsigned)((kp & 1) * 8704) + tx16, ty16, acc);
            if (kp < 7) {
                float* d = wsh + ((kp + 1) & 1) * 2176 + wk * 68 + wc;
                *(float4*)d = r0; *(float4*)(d + 4) = r1;
                __syncthreads();
            }
        }
        int c0 = cc * 64 + tx4;
        float4 bb = *(const float4*)(b2 + c0);
        float vals[4][4];
#pragma unroll
        for (int c = 0; c < 4; c++) {
            float lo, hi;
            asm("mov.b64 {%0,%1}, %2;" : "=f"(lo), "=f"(hi) : "l"(acc[c][0]));
            vals[0][c] = lo; vals[1][c] = hi;
            asm("mov.b64 {%0,%1}, %2;" : "=f"(lo), "=f"(hi) : "l"(acc[c][1]));
            vals[2][c] = lo; vals[3][c] = hi;
        }
#pragma unroll
        for (int ri = 0; ri < 4; ri++) {
            int r = ty4 + ri;
            float4 o;
            o.x = vals[ri][0] + bb.x; o.y = vals[ri][1] + bb.y;
            o.z = vals[ri][2] + bb.z; o.w = vals[ri][3] + bb.w;
            *(float4*)(tbuf + (size_t)r * 576 + 320 + c0) = o;
        }
    }
    __syncthreads();

    // -------- Phase 4: h2 = LN(relu(t2)); logits -> slog --------
#pragma unroll 1
    for (int rr = 0; rr < 8; rr++) {
        int row = rr * 8 + wid;
        const float* trow = tbuf + (size_t)row * 576 + 320;
        float v[8], s = 0.f, q = 0.f;
#pragma unroll
        for (int j = 0; j < 8; j++) {
            float xv = fmaxf(trow[lane + j * 32], 0.f);
            v[j] = xv; s += xv; q += xv * xv;
        }
        s = warp_sum(s); q = warp_sum(q);
        float mu = s * inv256, rstd = rsqrtf(q * inv256 - mu * mu + EPS);
        float l0 = 0.f, l1 = 0.f, l2 = 0.f, l3 = 0.f;
#pragma unroll
        for (int j = 0; j < 8; j++) {
            int c = lane + j * 32;
            float y = (v[j] - mu) * rstd * g2[c] + be2[c];
            float4 wp = *(const float4*)(wpre + (size_t)c * 4);
            l0 += y * wp.x; l1 += y * wp.y; l2 += y * wp.z; l3 += y * wp.w;
        }
        l0 = warp_sum(l0); l1 = warp_sum(l1); l2 = warp_sum(l2); l3 = warp_sum(l3);
        if (lane == 0) {
            bool mk = mask[n * 64 + row] != 0;
            slog[row * 4 + 0] = mk ? NEG : (l0 + bpre[0]);
            slog[row * 4 + 1] = mk ? NEG : (l1 + bpre[1]);
            slog[row * 4 + 2] = mk ? NEG : (l2 + bpre[2]);
            slog[row * 4 + 3] = mk ? NEG : (l3 + bpre[3]);
        }
    }
    __syncthreads();

    // -------- Phase 5: per-head top-16 softmax -> wsm --------
    if (wid < 4) {
        int h = wid;
        float v0 = slog[lane * 4 + h], v1 = slog[(32 + lane) * 4 + h];
        float c0 = v0, c1 = v1;
        float thr = NEG, maxv = NEG;
#pragma unroll 1
        for (int it = 0; it < 16; it++) {
            float loc = fmaxf(c0, c1);
            float m = warp_max(loc);
            if (it == 0) maxv = m;
            if (m == NEG) break;
            thr = m;
            unsigned bl = __ballot_sync(0xffffffffu, loc == m);
            int src = __ffs(bl) - 1;
            if (lane == src) { if (c0 == m) c0 = NEG; else c1 = NEG; }
        }
        float e0 = (v0 >= thr) ? expf(v0 - maxv) : 0.f;
        float e1 = (v1 >= thr) ? expf(v1 - maxv) : 0.f;
        float inv = 1.f / warp_sum(e0 + e1);
        wsm[h * 64 + lane] = e0 * inv;
        wsm[h * 64 + 32 + lane] = e1 * inv;
    }
    __syncthreads();

    // -------- Phase 6: agg[d,h] = sum_m w[h,m] * af[m,d]  (af in tbuf cols 256..319) --------
    {
        int d = t >> 2, h = t & 3;
        float s = 0.f;
#pragma unroll
        for (int m = 0; m < 64; m++) s += wsm[h * 64 + m] * tbuf[(size_t)m * 576 + 256 + d];
        aggs[t] = s;
    }
    __syncthreads();

    // -------- Phase 7: x_out = LN(relu(agg @ wg + bg)) --------
    {
        float v0a = 0.f, v1a = 0.f, v2a = 0.f, v3a = 0.f;
#pragma unroll 4
        for (int k = 0; k < 256; k += 4) {
            v0a += aggs[k]     * wg[(size_t)k * 256 + t];
            v1a += aggs[k + 1] * wg[(size_t)(k + 1) * 256 + t];
            v2a += aggs[k + 2] * wg[(size_t)(k + 2) * 256 + t];
            v3a += aggs[k + 3] * wg[(size_t)(k + 3) * 256 + t];
        }
        float v = fmaxf((v0a + v1a) + (v2a + v3a) + bg[t], 0.f);
        float s = warp_sum(v), q = warp_sum(v * v);
        if (lane == 0) { red[wid] = s; red[8 + wid] = q; }
        __syncthreads();
        if (t < 32) {
            float a = (lane < 8) ? red[lane] : 0.f;
            float b = (lane < 8) ? red[8 + lane] : 0.f;
#pragma unroll
            for (int o = 4; o; o >>= 1) {
                a += __shfl_xor_sync(0xffffffffu, a, o);
                b += __shfl_xor_sync(0xffffffffu, b, o);
            }
            if (lane == 0) { red[0] = a; red[8] = b; }
        }
        __syncthreads();
        float mu = red[0] * (1.f / 256.f), rstd = rsqrtf(red[8] * (1.f / 256.f) - mu * mu + EPS);
        float y = (v - mu) * rstd * gg[t] + beg[t];
        out[(size_t)n * 256 + t] = y;                 // x_out
        out[34078720ull + (size_t)n * 256 + t] = y;   // m (== x_out)
    }
}

// ---------------- launch ----------------
extern "C" void kernel_launch(void* const* d_in, const int* in_sizes, int n_in,
                              void* d_out, int out_size) {
    const float* x = (const float*)d_in[0];
    const float* iff = (const float*)d_in[1];
    const int* mask = (const int*)d_in[2];
    const int* ai = (const int*)d_in[3];
    const int* aj = (const int*)d_in[4];
    const float* w1 = (const float*)d_in[5], *b1 = (const float*)d_in[6];
    const float* g1 = (const float*)d_in[7], *be1 = (const float*)d_in[8];
    const float* w2 = (const float*)d_in[9], *b2 = (const float*)d_in[10];
    const float* g2 = (const float*)d_in[11], *be2 = (const float*)d_in[12];
    const float* wpre = (const float*)d_in[13], *bpre = (const float*)d_in[14];
    const float* watt = (const float*)d_in[15], *batt = (const float*)d_in[16];
    const float* gatt = (const float*)d_in[17], *beatt = (const float*)d_in[18];
    const float* wif = (const float*)d_in[19], *bif = (const float*)d_in[20];
    const float* gif = (const float*)d_in[21], *beif = (const float*)d_in[22];
    const float* wg = (const float*)d_in[23], *bg = (const float*)d_in[24];
    const float* gg = (const float*)d_in[25], *beg = (const float*)d_in[26];
    float* out = (float*)d_out;

    const int PS = (256 * 65 + 32 * 65) * 4;
    const int BS = (36864 + 16384 + 4352) * 4 + 128 * 4;  // 230,912 B
    cudaFuncSetAttribute(p_kernel, cudaFuncAttributeMaxDynamicSharedMemorySize, PS);
    cudaFuncSetAttribute(big_kernel, cudaFuncAttributeMaxDynamicSharedMemorySize, BS);

    pack_kernel<<<1728, 256>>>(w1, watt, wif, b1, batt, bif);
    p_kernel<<<dim3(32, 2), 256, PS>>>(x);
    big_kernel<<<2048, 256, BS>>>(iff, ai, aj, g1, be1, gatt, beatt, gif, beif,
                                  w2, b2, g2, be2, wpre, bpre, mask,
                                  wg, bg, gg, beg, out);
}